// round 16
// baseline (speedup 1.0000x reference)
#include <cuda_runtime.h>
#include <cuda_fp16.h>
#include <cstdint>
#include <math.h>

#define BB 4
#define SS 2048
#define DD 512
#define HH 8
#define DEPTH 64
#define BS (BB*SS)
#define LN_EPS 1e-6f

// fp16 scratch
__device__ __half g_xh[BS*DD];
__device__ __half g_wh[4*DD*DD];
__device__ __half g_qh[BS*DD];
__device__ __half g_kh[BS*DD];
__device__ __half g_vh[BS*DD];
__device__ __half g_ctxh[BS*DD];

#define SCALE2 0.18033688011112042f   // 0.125 * log2(e)

// ---------------------------------------------------------------------------
// helpers
// ---------------------------------------------------------------------------
__device__ __forceinline__ void mma_f16(float c[4], const uint32_t a[4], const uint32_t b0, const uint32_t b1) {
    asm volatile("mma.sync.aligned.m16n8k16.row.col.f32.f16.f16.f32 "
        "{%0,%1,%2,%3}, {%4,%5,%6,%7}, {%8,%9}, {%0,%1,%2,%3};"
        : "+f"(c[0]), "+f"(c[1]), "+f"(c[2]), "+f"(c[3])
        : "r"(a[0]), "r"(a[1]), "r"(a[2]), "r"(a[3]), "r"(b0), "r"(b1));
}
__device__ __forceinline__ void mma_h16(uint32_t c[2], const uint32_t a[4], const uint32_t b0, const uint32_t b1) {
    asm volatile("mma.sync.aligned.m16n8k16.row.col.f16.f16.f16.f16 "
        "{%0,%1}, {%2,%3,%4,%5}, {%6,%7}, {%0,%1};"
        : "+r"(c[0]), "+r"(c[1])
        : "r"(a[0]), "r"(a[1]), "r"(a[2]), "r"(a[3]), "r"(b0), "r"(b1));
}
__device__ __forceinline__ void ldsm4(uint32_t r[4], uint32_t addr) {
    asm volatile("ldmatrix.sync.aligned.m8n8.x4.shared.b16 {%0,%1,%2,%3}, [%4];"
        : "=r"(r[0]), "=r"(r[1]), "=r"(r[2]), "=r"(r[3]) : "r"(addr));
}
__device__ __forceinline__ void ldsm4t(uint32_t r[4], uint32_t addr) {
    asm volatile("ldmatrix.sync.aligned.m8n8.x4.trans.shared.b16 {%0,%1,%2,%3}, [%4];"
        : "=r"(r[0]), "=r"(r[1]), "=r"(r[2]), "=r"(r[3]) : "r"(addr));
}
__device__ __forceinline__ uint32_t packh2(float lo, float hi) {
    __half2 h = __floats2half2_rn(lo, hi);
    return *(uint32_t*)&h;
}
__device__ __forceinline__ uint32_t ex2h2(uint32_t x) {
    uint32_t y;
    asm("ex2.approx.f16x2 %0, %1;" : "=r"(y) : "r"(x));
    return y;
}
__device__ __forceinline__ void cp16(uint32_t dst, const void* src) {
    asm volatile("cp.async.cg.shared.global [%0], [%1], 16;" :: "r"(dst), "l"(src));
}
__device__ __forceinline__ void cp_commit() { asm volatile("cp.async.commit_group;"); }
template<int N>
__device__ __forceinline__ void cp_wait() { asm volatile("cp.async.wait_group %0;" :: "n"(N)); }

__device__ __forceinline__ uint32_t swz(uint32_t base, int r, int j) {
    return base + ((uint32_t)r << 7) + ((uint32_t)(j ^ (r & 7)) << 4);
}

__device__ __forceinline__ float2 dsmem_ld2(uint32_t addr, uint32_t rank) {
    uint32_t ra; float2 v;
    asm("mapa.shared::cluster.u32 %0, %1, %2;" : "=r"(ra) : "r"(addr), "r"(rank));
    asm("ld.shared::cluster.v2.f32 {%0,%1}, [%2];" : "=f"(v.x), "=f"(v.y) : "r"(ra));
    return v;
}
#define CLUSTER_ARRIVE() asm volatile("barrier.cluster.arrive.aligned;" ::: "memory")
#define CLUSTER_WAIT()   asm volatile("barrier.cluster.wait.aligned;" ::: "memory")

// ---------------------------------------------------------------------------
// combined fp32 -> fp16 converter (x + all 4 weights, one launch)
// ---------------------------------------------------------------------------
#define XN4 (BS*DD/4)
#define WN4 (DD*DD/4)
__global__ void cvt_all(const float* __restrict__ x,
                        const float* __restrict__ w0, const float* __restrict__ w1,
                        const float* __restrict__ w2, const float* __restrict__ w3,
                        __half* __restrict__ dx, __half* __restrict__ dw) {
    int i = blockIdx.x * 256 + threadIdx.x;
    const float* s;
    __half* d;
    size_t e;
    if (i < XN4) {
        s = x; d = dx; e = (size_t)i * 4;
    } else {
        int j = i - XN4;
        int z = j / WN4, k = j % WN4;
        s = (z == 0) ? w0 : (z == 1) ? w1 : (z == 2) ? w2 : w3;
        d = dw + (size_t)z * DD * DD;
        e = (size_t)k * 4;
    }
    float4 v = *(const float4*)&s[e];
    *(uint2*)&d[e] = make_uint2(packh2(v.x, v.y), packh2(v.z, v.w));
}

// ---------------------------------------------------------------------------
// fp16 GEMM (QKV): GBK=64, 2-stage cp.async, swizzled A, z grid. (R13 config)
// ---------------------------------------------------------------------------
#define GBM 128
#define GBN 128
#define GBK 64
#define GBH 136
#define A_STG 16384
#define B_STG (GBK*GBH*2)
#define GEMM_SMEM (2*(A_STG + B_STG))

__global__ __launch_bounds__(256, 2)
void gemm_qkv(const __half* __restrict__ A, const __half* __restrict__ Wbase,
              __half* __restrict__ Ch0, __half* __restrict__ Ch1, __half* __restrict__ Ch2) {
    extern __shared__ __align__(128) char smg[];
    const uint32_t sb = (uint32_t)__cvta_generic_to_shared(smg);
    const uint32_t sAu = sb;
    const uint32_t sBu = sb + 2 * A_STG;

    const int z = blockIdx.z;
    const __half* W = Wbase + (size_t)z * DD * DD;
    __half* Ch = (z == 0) ? Ch0 : (z == 1) ? Ch1 : Ch2;
    const float osc = (z == 0) ? SCALE2 : 1.0f;

    const int t = threadIdx.x;
    const int lane = t & 31, warp = t >> 5;
    const int g = lane >> 2, tig = lane & 3;
    const int wm = (warp >> 1) * 32;
    const int wn = (warp & 1) * 64;
    const int bm = blockIdx.y * GBM;
    const int bn = blockIdx.x * GBN;

    auto issue = [&](int ti, int st) {
        const int k0 = ti * GBK;
        const __half* Ap = A + (size_t)bm * DD + k0;
        const __half* Wp = W + (size_t)k0 * DD + bn;
        const uint32_t ab = sAu + (uint32_t)st * A_STG;
        const uint32_t bb = sBu + (uint32_t)st * B_STG;
        #pragma unroll
        for (int j = 0; j < 4; j++) {
            int idx = t + j * 256;
            int ar = idx >> 3, ac = idx & 7;
            cp16(swz(ab, ar, ac), Ap + (size_t)ar * DD + ac * 8);
            int br = idx >> 4, bc = idx & 15;
            cp16(bb + (uint32_t)(br * GBH + bc * 8) * 2,
                 Wp + (size_t)br * DD + bc * 8);
        }
    };

    float acc[2][8][4] = {};

    issue(0, 0); cp_commit();

    const int NKT = DD / GBK;   // 8
    for (int ti = 0; ti < NKT; ti++) {
        cp_wait<0>();
        __syncthreads();
        if (ti + 1 < NKT) { issue(ti + 1, (ti + 1) & 1); cp_commit(); }

        const uint32_t ab = sAu + (uint32_t)(ti & 1) * A_STG;
        const uint32_t bb = sBu + (uint32_t)(ti & 1) * B_STG;

        #pragma unroll
        for (int ks = 0; ks < 4; ks++) {
            uint32_t af[2][4];
            #pragma unroll
            for (int mt = 0; mt < 2; mt++) {
                int row = wm + mt * 16 + (lane & 15);
                int j = 2 * ks + ((lane >> 4) & 1);
                ldsm4(af[mt], swz(ab, row, j));
            }
            #pragma unroll
            for (int ntp = 0; ntp < 4; ntp++) {
                uint32_t bf[4];
                int row = ks * 16 + ((lane >> 3) & 1) * 8 + (lane & 7);
                int col = wn + ntp * 16 + ((lane >> 4) & 1) * 8;
                ldsm4t(bf, bb + (uint32_t)(row * GBH + col) * 2);
                #pragma unroll
                for (int mt = 0; mt < 2; mt++) {
                    mma_f16(acc[mt][ntp * 2    ], af[mt], bf[0], bf[1]);
                    mma_f16(acc[mt][ntp * 2 + 1], af[mt], bf[2], bf[3]);
                }
            }
        }
    }

    #pragma unroll
    for (int mt = 0; mt < 2; mt++) {
        #pragma unroll
        for (int nt = 0; nt < 8; nt++) {
            int col = bn + wn + nt * 8 + 2 * tig;
            #pragma unroll
            for (int h = 0; h < 2; h++) {
                int row = bm + wm + mt * 16 + g + h * 8;
                *(__half2*)&Ch[(size_t)row * DD + col] =
                    __floats2half2_rn(acc[mt][nt][h * 2] * osc,
                                      acc[mt][nt][h * 2 + 1] * osc);
            }
        }
    }
}

// ---------------------------------------------------------------------------
// Output projection + bias + residual + FUSED LayerNorm — lightweight CTAs:
// tile 64x128, 128 threads (4 warps x 32x64), 4 CTA/SM -> 512 CTAs ~ one
// full wave (vs 0.86 wave of 256 heavy CTAs). Cluster of 4 CTAs spans the
// 4 N-tiles of one 64-row stripe; LN partials exchanged via DSMEM.
// ---------------------------------------------------------------------------
#define OBM 64
#define OA_STG 8192                  // 64 rows * 128B swizzled
#define OB_STG (GBK*GBH*2)           // 17408
#define OUT_SMEM (2*(OA_STG + OB_STG))   // 51200

__global__ __launch_bounds__(128, 4) __cluster_dims__(4, 1, 1)
void gemm_out_ln(const __half* __restrict__ A, const __half* __restrict__ W,
                 const float* __restrict__ bias, const float* __restrict__ resid,
                 const float* __restrict__ gamma, const float* __restrict__ beta,
                 float* __restrict__ out) {
    extern __shared__ __align__(128) char smg[];
    const uint32_t sb = (uint32_t)__cvta_generic_to_shared(smg);
    const uint32_t sAu = sb;
    const uint32_t sBu = sb + 2 * OA_STG;

    __shared__ float2 part[OBM][2];
    __shared__ float2 csum[OBM];
    __shared__ float2 tot[OBM];

    const int t = threadIdx.x;
    const int lane = t & 31, warp = t >> 5;
    const int g = lane >> 2, tig = lane & 3;
    const int wm = (warp >> 1) * 32;     // 2 warps along M (64 rows)
    const int wn = (warp & 1) * 64;      // 2 warps along N (128 cols)
    const int bm = blockIdx.y * OBM;
    const int bn = blockIdx.x * 128;

    // A: 64 rows x 8 chunks = 512 -> 4/thread; B: 64 rows x 16 chunks = 1024 -> 8/thread
    auto issue = [&](int ti, int st) {
        const int k0 = ti * GBK;
        const __half* Ap = A + (size_t)bm * DD + k0;
        const __half* Wp = W + (size_t)k0 * DD + bn;
        const uint32_t ab = sAu + (uint32_t)st * OA_STG;
        const uint32_t bb = sBu + (uint32_t)st * OB_STG;
        #pragma unroll
        for (int j = 0; j < 4; j++) {
            int idx = t + j * 128;
            int ar = idx >> 3, ac = idx & 7;
            cp16(swz(ab, ar, ac), Ap + (size_t)ar * DD + ac * 8);
        }
        #pragma unroll
        for (int j = 0; j < 8; j++) {
            int idx = t + j * 128;
            int br = idx >> 4, bc = idx & 15;
            cp16(bb + (uint32_t)(br * GBH + bc * 8) * 2,
                 Wp + (size_t)br * DD + bc * 8);
        }
    };

    float acc[2][8][4] = {};

    issue(0, 0); cp_commit();

    const int NKT = DD / GBK;   // 8
    for (int ti = 0; ti < NKT; ti++) {
        cp_wait<0>();
        __syncthreads();
        if (ti + 1 < NKT) { issue(ti + 1, (ti + 1) & 1); cp_commit(); }

        const uint32_t ab = sAu + (uint32_t)(ti & 1) * OA_STG;
        const uint32_t bb = sBu + (uint32_t)(ti & 1) * OB_STG;

        #pragma unroll
        for (int ks = 0; ks < 4; ks++) {
            uint32_t af[2][4];
            #pragma unroll
            for (int mt = 0; mt < 2; mt++) {
                int row = wm + mt * 16 + (lane & 15);
                int j = 2 * ks + ((lane >> 4) & 1);
                ldsm4(af[mt], swz(ab, row, j));
            }
            #pragma unroll
            for (int ntp = 0; ntp < 4; ntp++) {
                uint32_t bf[4];
                int row = ks * 16 + ((lane >> 3) & 1) * 8 + (lane & 7);
                int col = wn + ntp * 16 + ((lane >> 4) & 1) * 8;
                ldsm4t(bf, bb + (uint32_t)(row * GBH + col) * 2);
                #pragma unroll
                for (int mt = 0; mt < 2; mt++) {
                    mma_f16(acc[mt][ntp * 2    ], af[mt], bf[0], bf[1]);
                    mma_f16(acc[mt][ntp * 2 + 1], af[mt], bf[2], bf[3]);
                }
            }
        }
    }

    // ---- epilogue: resid+bias, per-row partials ----
    #pragma unroll
    for (int mt = 0; mt < 2; mt++) {
        #pragma unroll
        for (int h = 0; h < 2; h++) {
            int rowl = wm + mt * 16 + g + h * 8;
            int row  = bm + rowl;
            float s = 0.0f, q = 0.0f;
            #pragma unroll
            for (int nt = 0; nt < 8; nt++) {
                int col = bn + wn + nt * 8 + 2 * tig;
                float2 bb = *(const float2*)&bias[col];
                float2 rr = *(const float2*)&resid[(size_t)row * DD + col];
                float v0 = acc[mt][nt][h * 2 + 0] + bb.x + rr.x;
                float v1 = acc[mt][nt][h * 2 + 1] + bb.y + rr.y;
                acc[mt][nt][h * 2 + 0] = v0;
                acc[mt][nt][h * 2 + 1] = v1;
                s += v0 + v1;
                q += v0 * v0 + v1 * v1;
            }
            s += __shfl_xor_sync(0xFFFFFFFFu, s, 1);
            s += __shfl_xor_sync(0xFFFFFFFFu, s, 2);
            q += __shfl_xor_sync(0xFFFFFFFFu, q, 1);
            q += __shfl_xor_sync(0xFFFFFFFFu, q, 2);
            if (tig == 0) part[rowl][warp & 1] = make_float2(s, q);
        }
    }
    __syncthreads();
    if (t < OBM) {
        float2 a = part[t][0], b = part[t][1];
        csum[t] = make_float2(a.x + b.x, a.y + b.y);
    }
    CLUSTER_ARRIVE();
    CLUSTER_WAIT();
    if (t < OBM) {
        uint32_t ca = (uint32_t)__cvta_generic_to_shared(&csum[t]);
        float s = 0.0f, q = 0.0f;
        #pragma unroll
        for (int rk = 0; rk < 4; rk++) {
            float2 v = dsmem_ld2(ca, rk);
            s += v.x; q += v.y;
        }
        tot[t] = make_float2(s, q);
    }
    __syncthreads();

    // ---- normalize + write out ----
    #pragma unroll
    for (int mt = 0; mt < 2; mt++) {
        #pragma unroll
        for (int h = 0; h < 2; h++) {
            int rowl = wm + mt * 16 + g + h * 8;
            int row  = bm + rowl;
            float2 tv = tot[rowl];
            float mu  = tv.x * (1.0f / DD);
            float var = tv.y * (1.0f / DD) - mu * mu;
            float inv = rsqrtf(var + LN_EPS);
            #pragma unroll
            for (int nt = 0; nt < 8; nt++) {
                int col = bn + wn + nt * 8 + 2 * tig;
                float2 gm = *(const float2*)&gamma[col];
                float2 bt = *(const float2*)&beta[col];
                float o0 = (acc[mt][nt][h * 2 + 0] - mu) * inv * gm.x + bt.x;
                float o1 = (acc[mt][nt][h * 2 + 1] - mu) * inv * gm.y + bt.y;
                *(float2*)&out[(size_t)row * DD + col] = make_float2(o0, o1);
            }
        }
    }

    CLUSTER_ARRIVE();
    CLUSTER_WAIT();
}

// ---------------------------------------------------------------------------
// Flash attention (best measured config, unchanged).
// ---------------------------------------------------------------------------
#define AQT 128
#define AKT 64
#define SQ_OFF 0
#define SK_OFF (128*128)
#define SV_OFF (SK_OFF + 2*64*128)
#define ATTN_SMEM (SV_OFF + 2*64*128)   // 49152

__global__ __launch_bounds__(128, 4)
void attn_h(const __half* __restrict__ Q, const __half* __restrict__ K,
            const __half* __restrict__ V, __half* __restrict__ O) {
    extern __shared__ __align__(128) char sma[];
    const uint32_t sb = (uint32_t)__cvta_generic_to_shared(sma);
    const uint32_t sQu = sb + SQ_OFF;
    const uint32_t sKu = sb + SK_OFF;
    const uint32_t sVu = sb + SV_OFF;

    const int t = threadIdx.x;
    const int lane = t & 31, warp = t >> 5;
    const int g = lane >> 2, tig = lane & 3;

    const int bh = blockIdx.y;
    const int b = bh / HH, h = bh % HH;
    const int q0 = blockIdx.x * AQT;
    const size_t base = (size_t)b * SS * DD + (size_t)h * DEPTH;
    const int wrow = warp * 32;

    const int kr = t >> 3, kj = t & 7;
    auto issue = [&](int ti, int bi) {
        const __half* Kp = K + base + (size_t)(ti * AKT) * DD + kj * 8;
        const __half* Vp = V + base + (size_t)(ti * AKT) * DD + kj * 8;
        const uint32_t kb = sKu + (uint32_t)bi * 8192;
        const uint32_t vb = sVu + (uint32_t)bi * 8192;
        #pragma unroll
        for (int j = 0; j < 4; j++) {
            int r = kr + j * 16;
            cp16(swz(kb, r, kj), Kp + (size_t)r * DD);
            cp16(swz(vb, r, kj), Vp + (size_t)r * DD);
        }
    };

    {
        const __half* Qp = Q + base + (size_t)q0 * DD;
        #pragma unroll
        for (int j = 0; j < 8; j++) {
            int idx = t + j * 128;
            int r = idx >> 3, jj = idx & 7;
            cp16(swz(sQu, r, jj), Qp + (size_t)r * DD + jj * 8);
        }
    }
    issue(0, 0);
    cp_commit();

    float o[2][8][4] = {};
    float sum[2][2] = {};

    const int NT = SS / AKT;
    for (int ti = 0; ti < NT; ti++) {
        cp_wait<0>();
        __syncthreads();
        if (ti + 1 < NT) { issue(ti + 1, (ti + 1) & 1); cp_commit(); }

        const uint32_t kb = sKu + (uint32_t)(ti & 1) * 8192;
        const uint32_t vb = sVu + (uint32_t)(ti & 1) * 8192;

        uint32_t sh[2][8][2] = {};
        #pragma unroll
        for (int ks = 0; ks < 4; ks++) {
            uint32_t af[2][4];
            #pragma unroll
            for (int mt = 0; mt < 2; mt++) {
                int row = wrow + mt * 16 + (lane & 15);
                int j = 2 * ks + ((lane >> 4) & 1);
                ldsm4(af[mt], swz(sQu, row, j));
            }
            #pragma unroll
            for (int ntp = 0; ntp < 4; ntp++) {
                uint32_t bf[4];
                int row = ntp * 16 + ((lane >> 4) & 1) * 8 + (lane & 7);
                int j = 2 * ks + ((lane >> 3) & 1);
                ldsm4(bf, swz(kb, row, j));
                #pragma unroll
                for (int mt = 0; mt < 2; mt++) {
                    mma_h16(sh[mt][ntp * 2    ], af[mt], bf[0], bf[1]);
                    mma_h16(sh[mt][ntp * 2 + 1], af[mt], bf[2], bf[3]);
                }
            }
        }

        #pragma unroll
        for (int mt = 0; mt < 2; mt++) {
            __half2 t0 = __float2half2_rn(0.0f), t1 = __float2half2_rn(0.0f);
            #pragma unroll
            for (int nt = 0; nt < 8; nt++) {
                sh[mt][nt][0] = ex2h2(sh[mt][nt][0]);
                sh[mt][nt][1] = ex2h2(sh[mt][nt][1]);
                t0 = __hadd2(t0, *(__half2*)&sh[mt][nt][0]);
                t1 = __hadd2(t1, *(__half2*)&sh[mt][nt][1]);
            }
            float2 f0 = __half22float2(t0), f1 = __half22float2(t1);
            sum[mt][0] += f0.x + f0.y;
            sum[mt][1] += f1.x + f1.y;
        }

        #pragma unroll
        for (int j = 0; j < 4; j++) {
            #pragma unroll
            for (int ntp = 0; ntp < 4; ntp++) {
                uint32_t bf[4];
                int row = j * 16 + ((lane >> 3) & 1) * 8 + (lane & 7);
                int jj = 2 * ntp + ((lane >> 4) & 1);
                ldsm4t(bf, swz(vb, row, jj));
                #pragma unroll
                for (int mt = 0; mt < 2; mt++) {
                    uint32_t af[4] = { sh[mt][2*j][0], sh[mt][2*j][1],
                                       sh[mt][2*j+1][0], sh[mt][2*j+1][1] };
                    mma_f16(o[mt][ntp * 2    ], af, bf[0], bf[1]);
                    mma_f16(o[mt][ntp * 2 + 1], af, bf[2], bf[3]);
                }
            }
        }
    }

    #pragma unroll
    for (int mt = 0; mt < 2; mt++) {
        #pragma unroll
        for (int hh = 0; hh < 2; hh++) {
            sum[mt][hh] += __shfl_xor_sync(0xFFFFFFFFu, sum[mt][hh], 1);
            sum[mt][hh] += __shfl_xor_sync(0xFFFFFFFFu, sum[mt][hh], 2);
        }
    }

    #pragma unroll
    for (int mt = 0; mt < 2; mt++) {
        float inv0 = 1.0f / sum[mt][0], inv1 = 1.0f / sum[mt][1];
        #pragma unroll
        for (int nt = 0; nt < 8; nt++) {
            int d = nt * 8 + 2 * tig;
            size_t r0i = base + (size_t)(q0 + wrow + mt * 16 + g    ) * DD + d;
            size_t r1i = base + (size_t)(q0 + wrow + mt * 16 + g + 8) * DD + d;
            *(__half2*)&O[r0i] = __floats2half2_rn(o[mt][nt][0] * inv0, o[mt][nt][1] * inv0);
            *(__half2*)&O[r1i] = __floats2half2_rn(o[mt][nt][2] * inv1, o[mt][nt][3] * inv1);
        }
    }
}

// ---------------------------------------------------------------------------
extern "C" void kernel_launch(void* const* d_in, const int* in_sizes, int n_in,
                              void* d_out, int out_size) {
    const float* x     = (const float*)d_in[0];
    const float* wq    = (const float*)d_in[1];
    const float* wk    = (const float*)d_in[2];
    const float* wv    = (const float*)d_in[3];
    const float* wo    = (const float*)d_in[4];
    const float* bo    = (const float*)d_in[5];
    const float* gamma = (const float*)d_in[6];
    const float* beta  = (const float*)d_in[7];
    float* out = (float*)d_out;

    __half *pxh, *pwh, *pqh, *pkh, *pvh, *pctxh;
    cudaGetSymbolAddress((void**)&pxh,   g_xh);
    cudaGetSymbolAddress((void**)&pwh,   g_wh);
    cudaGetSymbolAddress((void**)&pqh,   g_qh);
    cudaGetSymbolAddress((void**)&pkh,   g_kh);
    cudaGetSymbolAddress((void**)&pvh,   g_vh);
    cudaGetSymbolAddress((void**)&pctxh, g_ctxh);

    cudaFuncSetAttribute(gemm_qkv,    cudaFuncAttributeMaxDynamicSharedMemorySize, GEMM_SMEM);
    cudaFuncSetAttribute(gemm_out_ln, cudaFuncAttributeMaxDynamicSharedMemorySize, OUT_SMEM);
    cudaFuncSetAttribute(attn_h,      cudaFuncAttributeMaxDynamicSharedMemorySize, ATTN_SMEM);

    cvt_all<<<(XN4 + 4 * WN4) / 256, 256>>>(x, wq, wk, wv, wo, pxh, pwh);

    dim3 qkvgrid(DD / GBN, BS / GBM, 3);
    gemm_qkv<<<qkvgrid, 256, GEMM_SMEM>>>(pxh, pwh, pqh, pkh, pvh);

    dim3 agrid(SS / AQT, BB * HH);
    attn_h<<<agrid, 128, ATTN_SMEM>>>(pqh, pkh, pvh, pctxh);

    // output projection + bias + residual + fused LayerNorm
    // lightweight 64x128 tiles: 512 CTAs, 4 CTA/SM, clusters of 4 N-tiles
    dim3 ogrid(DD / 128, BS / OBM);
    gemm_out_ln<<<ogrid, 128, OUT_SMEM>>>(pctxh, pwh + (size_t)3 * DD * DD,
                                          bo, x, gamma, beta, out);
}

// round 17
// speedup vs baseline: 1.0104x; 1.0104x over previous
#include <cuda_runtime.h>
#include <cuda_fp16.h>
#include <cstdint>
#include <math.h>

#define BB 4
#define SS 2048
#define DD 512
#define HH 8
#define DEPTH 64
#define BS (BB*SS)
#define LN_EPS 1e-6f

// fp16 scratch
__device__ __half g_xh[BS*DD];
__device__ __half g_wh[4*DD*DD];
__device__ __half g_qh[BS*DD];
__device__ __half g_kh[BS*DD];
__device__ __half g_vh[BS*DD];
__device__ __half g_ctxh[BS*DD];

#define SCALE2 0.18033688011112042f   // 0.125 * log2(e)

// ---------------------------------------------------------------------------
// helpers
// ---------------------------------------------------------------------------
__device__ __forceinline__ void mma_f16(float c[4], const uint32_t a[4], const uint32_t b0, const uint32_t b1) {
    asm volatile("mma.sync.aligned.m16n8k16.row.col.f32.f16.f16.f32 "
        "{%0,%1,%2,%3}, {%4,%5,%6,%7}, {%8,%9}, {%0,%1,%2,%3};"
        : "+f"(c[0]), "+f"(c[1]), "+f"(c[2]), "+f"(c[3])
        : "r"(a[0]), "r"(a[1]), "r"(a[2]), "r"(a[3]), "r"(b0), "r"(b1));
}
__device__ __forceinline__ void mma_h16(uint32_t c[2], const uint32_t a[4], const uint32_t b0, const uint32_t b1) {
    asm volatile("mma.sync.aligned.m16n8k16.row.col.f16.f16.f16.f16 "
        "{%0,%1}, {%2,%3,%4,%5}, {%6,%7}, {%0,%1};"
        : "+r"(c[0]), "+r"(c[1])
        : "r"(a[0]), "r"(a[1]), "r"(a[2]), "r"(a[3]), "r"(b0), "r"(b1));
}
__device__ __forceinline__ void ldsm4(uint32_t r[4], uint32_t addr) {
    asm volatile("ldmatrix.sync.aligned.m8n8.x4.shared.b16 {%0,%1,%2,%3}, [%4];"
        : "=r"(r[0]), "=r"(r[1]), "=r"(r[2]), "=r"(r[3]) : "r"(addr));
}
__device__ __forceinline__ void ldsm4t(uint32_t r[4], uint32_t addr) {
    asm volatile("ldmatrix.sync.aligned.m8n8.x4.trans.shared.b16 {%0,%1,%2,%3}, [%4];"
        : "=r"(r[0]), "=r"(r[1]), "=r"(r[2]), "=r"(r[3]) : "r"(addr));
}
__device__ __forceinline__ uint32_t packh2(float lo, float hi) {
    __half2 h = __floats2half2_rn(lo, hi);
    return *(uint32_t*)&h;
}
__device__ __forceinline__ uint32_t ex2h2(uint32_t x) {
    uint32_t y;
    asm("ex2.approx.f16x2 %0, %1;" : "=r"(y) : "r"(x));
    return y;
}
__device__ __forceinline__ void cp16(uint32_t dst, const void* src) {
    asm volatile("cp.async.cg.shared.global [%0], [%1], 16;" :: "r"(dst), "l"(src));
}
__device__ __forceinline__ void cp_commit() { asm volatile("cp.async.commit_group;"); }
template<int N>
__device__ __forceinline__ void cp_wait() { asm volatile("cp.async.wait_group %0;" :: "n"(N)); }

__device__ __forceinline__ uint32_t swz(uint32_t base, int r, int j) {
    return base + ((uint32_t)r << 7) + ((uint32_t)(j ^ (r & 7)) << 4);
}

// push-model DSMEM store: write v to the same smem offset in cluster CTA `rank`
__device__ __forceinline__ void dsmem_st2(uint32_t addr, uint32_t rank, float2 v) {
    uint32_t ra;
    asm("mapa.shared::cluster.u32 %0, %1, %2;" : "=r"(ra) : "r"(addr), "r"(rank));
    asm volatile("st.shared::cluster.v2.f32 [%0], {%1,%2};"
                 :: "r"(ra), "f"(v.x), "f"(v.y) : "memory");
}
__device__ __forceinline__ uint32_t cta_rank() {
    uint32_t r;
    asm("mov.u32 %0, %%cluster_ctarank;" : "=r"(r));
    return r;
}
#define CLUSTER_ARRIVE() asm volatile("barrier.cluster.arrive.aligned;" ::: "memory")
#define CLUSTER_WAIT()   asm volatile("barrier.cluster.wait.aligned;" ::: "memory")

// ---------------------------------------------------------------------------
// combined fp32 -> fp16 converter (x + all 4 weights, one launch)
// ---------------------------------------------------------------------------
#define XN4 (BS*DD/4)
#define WN4 (DD*DD/4)
__global__ void cvt_all(const float* __restrict__ x,
                        const float* __restrict__ w0, const float* __restrict__ w1,
                        const float* __restrict__ w2, const float* __restrict__ w3,
                        __half* __restrict__ dx, __half* __restrict__ dw) {
    int i = blockIdx.x * 256 + threadIdx.x;
    const float* s;
    __half* d;
    size_t e;
    if (i < XN4) {
        s = x; d = dx; e = (size_t)i * 4;
    } else {
        int j = i - XN4;
        int z = j / WN4, k = j % WN4;
        s = (z == 0) ? w0 : (z == 1) ? w1 : (z == 2) ? w2 : w3;
        d = dw + (size_t)z * DD * DD;
        e = (size_t)k * 4;
    }
    float4 v = *(const float4*)&s[e];
    *(uint2*)&d[e] = make_uint2(packh2(v.x, v.y), packh2(v.z, v.w));
}

// ---------------------------------------------------------------------------
// fp16 GEMM (QKV): GBK=64, 2-stage cp.async, swizzled A, z grid. (R13 config)
// ---------------------------------------------------------------------------
#define GBM 128
#define GBN 128
#define GBK 64
#define GBH 136
#define A_STG 16384
#define B_STG (GBK*GBH*2)
#define GEMM_SMEM (2*(A_STG + B_STG))

__global__ __launch_bounds__(256, 2)
void gemm_qkv(const __half* __restrict__ A, const __half* __restrict__ Wbase,
              __half* __restrict__ Ch0, __half* __restrict__ Ch1, __half* __restrict__ Ch2) {
    extern __shared__ __align__(128) char smg[];
    const uint32_t sb = (uint32_t)__cvta_generic_to_shared(smg);
    const uint32_t sAu = sb;
    const uint32_t sBu = sb + 2 * A_STG;

    const int z = blockIdx.z;
    const __half* W = Wbase + (size_t)z * DD * DD;
    __half* Ch = (z == 0) ? Ch0 : (z == 1) ? Ch1 : Ch2;
    const float osc = (z == 0) ? SCALE2 : 1.0f;

    const int t = threadIdx.x;
    const int lane = t & 31, warp = t >> 5;
    const int g = lane >> 2, tig = lane & 3;
    const int wm = (warp >> 1) * 32;
    const int wn = (warp & 1) * 64;
    const int bm = blockIdx.y * GBM;
    const int bn = blockIdx.x * GBN;

    auto issue = [&](int ti, int st) {
        const int k0 = ti * GBK;
        const __half* Ap = A + (size_t)bm * DD + k0;
        const __half* Wp = W + (size_t)k0 * DD + bn;
        const uint32_t ab = sAu + (uint32_t)st * A_STG;
        const uint32_t bb = sBu + (uint32_t)st * B_STG;
        #pragma unroll
        for (int j = 0; j < 4; j++) {
            int idx = t + j * 256;
            int ar = idx >> 3, ac = idx & 7;
            cp16(swz(ab, ar, ac), Ap + (size_t)ar * DD + ac * 8);
            int br = idx >> 4, bc = idx & 15;
            cp16(bb + (uint32_t)(br * GBH + bc * 8) * 2,
                 Wp + (size_t)br * DD + bc * 8);
        }
    };

    float acc[2][8][4] = {};

    issue(0, 0); cp_commit();

    const int NKT = DD / GBK;   // 8
    for (int ti = 0; ti < NKT; ti++) {
        cp_wait<0>();
        __syncthreads();
        if (ti + 1 < NKT) { issue(ti + 1, (ti + 1) & 1); cp_commit(); }

        const uint32_t ab = sAu + (uint32_t)(ti & 1) * A_STG;
        const uint32_t bb = sBu + (uint32_t)(ti & 1) * B_STG;

        #pragma unroll
        for (int ks = 0; ks < 4; ks++) {
            uint32_t af[2][4];
            #pragma unroll
            for (int mt = 0; mt < 2; mt++) {
                int row = wm + mt * 16 + (lane & 15);
                int j = 2 * ks + ((lane >> 4) & 1);
                ldsm4(af[mt], swz(ab, row, j));
            }
            #pragma unroll
            for (int ntp = 0; ntp < 4; ntp++) {
                uint32_t bf[4];
                int row = ks * 16 + ((lane >> 3) & 1) * 8 + (lane & 7);
                int col = wn + ntp * 16 + ((lane >> 4) & 1) * 8;
                ldsm4t(bf, bb + (uint32_t)(row * GBH + col) * 2);
                #pragma unroll
                for (int mt = 0; mt < 2; mt++) {
                    mma_f16(acc[mt][ntp * 2    ], af[mt], bf[0], bf[1]);
                    mma_f16(acc[mt][ntp * 2 + 1], af[mt], bf[2], bf[3]);
                }
            }
        }
    }

    #pragma unroll
    for (int mt = 0; mt < 2; mt++) {
        #pragma unroll
        for (int nt = 0; nt < 8; nt++) {
            int col = bn + wn + nt * 8 + 2 * tig;
            #pragma unroll
            for (int h = 0; h < 2; h++) {
                int row = bm + wm + mt * 16 + g + h * 8;
                *(__half2*)&Ch[(size_t)row * DD + col] =
                    __floats2half2_rn(acc[mt][nt][h * 2] * osc,
                                      acc[mt][nt][h * 2 + 1] * osc);
            }
        }
    }
}

// ---------------------------------------------------------------------------
// Output projection + bias + residual + FUSED LayerNorm (R14 shape: 128x128
// tile, 256 threads, 2 CTA/SM) with PUSH-model single-barrier LN exchange:
// each CTA stores its partial into slot [rank] of every peer's tot4 via
// st.shared::cluster, ONE cluster barrier, then local 4-way add. Removes one
// barrier + remote-read chain + exit barrier vs the pull model.
// ---------------------------------------------------------------------------
__global__ __launch_bounds__(256, 2) __cluster_dims__(4, 1, 1)
void gemm_out_ln(const __half* __restrict__ A, const __half* __restrict__ W,
                 const float* __restrict__ bias, const float* __restrict__ resid,
                 const float* __restrict__ gamma, const float* __restrict__ beta,
                 float* __restrict__ out) {
    extern __shared__ __align__(128) char smg[];
    const uint32_t sb = (uint32_t)__cvta_generic_to_shared(smg);
    const uint32_t sAu = sb;
    const uint32_t sBu = sb + 2 * A_STG;

    __shared__ float2 part[128][2];
    __shared__ float2 tot4[128][4];

    const int t = threadIdx.x;
    const int lane = t & 31, warp = t >> 5;
    const int g = lane >> 2, tig = lane & 3;
    const int wm = (warp >> 1) * 32;
    const int wn = (warp & 1) * 64;
    const int bm = blockIdx.y * GBM;
    const int bn = blockIdx.x * GBN;
    const uint32_t myrank = cta_rank();

    auto issue = [&](int ti, int st) {
        const int k0 = ti * GBK;
        const __half* Ap = A + (size_t)bm * DD + k0;
        const __half* Wp = W + (size_t)k0 * DD + bn;
        const uint32_t ab = sAu + (uint32_t)st * A_STG;
        const uint32_t bb = sBu + (uint32_t)st * B_STG;
        #pragma unroll
        for (int j = 0; j < 4; j++) {
            int idx = t + j * 256;
            int ar = idx >> 3, ac = idx & 7;
            cp16(swz(ab, ar, ac), Ap + (size_t)ar * DD + ac * 8);
            int br = idx >> 4, bc = idx & 15;
            cp16(bb + (uint32_t)(br * GBH + bc * 8) * 2,
                 Wp + (size_t)br * DD + bc * 8);
        }
    };

    float acc[2][8][4] = {};

    issue(0, 0); cp_commit();

    const int NKT = DD / GBK;
    for (int ti = 0; ti < NKT; ti++) {
        cp_wait<0>();
        __syncthreads();
        if (ti + 1 < NKT) { issue(ti + 1, (ti + 1) & 1); cp_commit(); }

        const uint32_t ab = sAu + (uint32_t)(ti & 1) * A_STG;
        const uint32_t bb = sBu + (uint32_t)(ti & 1) * B_STG;

        #pragma unroll
        for (int ks = 0; ks < 4; ks++) {
            uint32_t af[2][4];
            #pragma unroll
            for (int mt = 0; mt < 2; mt++) {
                int row = wm + mt * 16 + (lane & 15);
                int j = 2 * ks + ((lane >> 4) & 1);
                ldsm4(af[mt], swz(ab, row, j));
            }
            #pragma unroll
            for (int ntp = 0; ntp < 4; ntp++) {
                uint32_t bf[4];
                int row = ks * 16 + ((lane >> 3) & 1) * 8 + (lane & 7);
                int col = wn + ntp * 16 + ((lane >> 4) & 1) * 8;
                ldsm4t(bf, bb + (uint32_t)(row * GBH + col) * 2);
                #pragma unroll
                for (int mt = 0; mt < 2; mt++) {
                    mma_f16(acc[mt][ntp * 2    ], af[mt], bf[0], bf[1]);
                    mma_f16(acc[mt][ntp * 2 + 1], af[mt], bf[2], bf[3]);
                }
            }
        }
    }

    // ---- epilogue: resid+bias, per-row partials ----
    #pragma unroll
    for (int mt = 0; mt < 2; mt++) {
        #pragma unroll
        for (int h = 0; h < 2; h++) {
            int rowl = wm + mt * 16 + g + h * 8;
            int row  = bm + rowl;
            float s = 0.0f, q = 0.0f;
            #pragma unroll
            for (int nt = 0; nt < 8; nt++) {
                int col = bn + wn + nt * 8 + 2 * tig;
                float2 bb = *(const float2*)&bias[col];
                float2 rr = *(const float2*)&resid[(size_t)row * DD + col];
                float v0 = acc[mt][nt][h * 2 + 0] + bb.x + rr.x;
                float v1 = acc[mt][nt][h * 2 + 1] + bb.y + rr.y;
                acc[mt][nt][h * 2 + 0] = v0;
                acc[mt][nt][h * 2 + 1] = v1;
                s += v0 + v1;
                q += v0 * v0 + v1 * v1;
            }
            s += __shfl_xor_sync(0xFFFFFFFFu, s, 1);
            s += __shfl_xor_sync(0xFFFFFFFFu, s, 2);
            q += __shfl_xor_sync(0xFFFFFFFFu, q, 1);
            q += __shfl_xor_sync(0xFFFFFFFFu, q, 2);
            if (tig == 0) part[rowl][warp & 1] = make_float2(s, q);
        }
    }
    __syncthreads();
    // push combined CTA partial to slot [myrank] of every cluster peer
    if (t < 128) {
        float2 a = part[t][0], b = part[t][1];
        float2 c = make_float2(a.x + b.x, a.y + b.y);
        uint32_t addr = (uint32_t)__cvta_generic_to_shared(&tot4[t][myrank]);
        #pragma unroll
        for (uint32_t rk = 0; rk < 4; rk++)
            dsmem_st2(addr, rk, c);
    }
    CLUSTER_ARRIVE();
    CLUSTER_WAIT();
    __syncthreads();

    // ---- normalize + write out (all data now local) ----
    #pragma unroll
    for (int mt = 0; mt < 2; mt++) {
        #pragma unroll
        for (int h = 0; h < 2; h++) {
            int rowl = wm + mt * 16 + g + h * 8;
            int row  = bm + rowl;
            float2 t0 = tot4[rowl][0], t1 = tot4[rowl][1];
            float2 t2 = tot4[rowl][2], t3 = tot4[rowl][3];
            float sx = t0.x + t1.x + t2.x + t3.x;
            float sq = t0.y + t1.y + t2.y + t3.y;
            float mu  = sx * (1.0f / DD);
            float var = sq * (1.0f / DD) - mu * mu;
            float inv = rsqrtf(var + LN_EPS);
            #pragma unroll
            for (int nt = 0; nt < 8; nt++) {
                int col = bn + wn + nt * 8 + 2 * tig;
                float2 gm = *(const float2*)&gamma[col];
                float2 bt = *(const float2*)&beta[col];
                float o0 = (acc[mt][nt][h * 2 + 0] - mu) * inv * gm.x + bt.x;
                float o1 = (acc[mt][nt][h * 2 + 1] - mu) * inv * gm.y + bt.y;
                *(float2*)&out[(size_t)row * DD + col] = make_float2(o0, o1);
            }
        }
    }
}

// ---------------------------------------------------------------------------
// Flash attention (best measured config, unchanged).
// ---------------------------------------------------------------------------
#define AQT 128
#define AKT 64
#define SQ_OFF 0
#define SK_OFF (128*128)
#define SV_OFF (SK_OFF + 2*64*128)
#define ATTN_SMEM (SV_OFF + 2*64*128)   // 49152

__global__ __launch_bounds__(128, 4)
void attn_h(const __half* __restrict__ Q, const __half* __restrict__ K,
            const __half* __restrict__ V, __half* __restrict__ O) {
    extern __shared__ __align__(128) char sma[];
    const uint32_t sb = (uint32_t)__cvta_generic_to_shared(sma);
    const uint32_t sQu = sb + SQ_OFF;
    const uint32_t sKu = sb + SK_OFF;
    const uint32_t sVu = sb + SV_OFF;

    const int t = threadIdx.x;
    const int lane = t & 31, warp = t >> 5;
    const int g = lane >> 2, tig = lane & 3;

    const int bh = blockIdx.y;
    const int b = bh / HH, h = bh % HH;
    const int q0 = blockIdx.x * AQT;
    const size_t base = (size_t)b * SS * DD + (size_t)h * DEPTH;
    const int wrow = warp * 32;

    const int kr = t >> 3, kj = t & 7;
    auto issue = [&](int ti, int bi) {
        const __half* Kp = K + base + (size_t)(ti * AKT) * DD + kj * 8;
        const __half* Vp = V + base + (size_t)(ti * AKT) * DD + kj * 8;
        const uint32_t kb = sKu + (uint32_t)bi * 8192;
        const uint32_t vb = sVu + (uint32_t)bi * 8192;
        #pragma unroll
        for (int j = 0; j < 4; j++) {
            int r = kr + j * 16;
            cp16(swz(kb, r, kj), Kp + (size_t)r * DD);
            cp16(swz(vb, r, kj), Vp + (size_t)r * DD);
        }
    };

    {
        const __half* Qp = Q + base + (size_t)q0 * DD;
        #pragma unroll
        for (int j = 0; j < 8; j++) {
            int idx = t + j * 128;
            int r = idx >> 3, jj = idx & 7;
            cp16(swz(sQu, r, jj), Qp + (size_t)r * DD + jj * 8);
        }
    }
    issue(0, 0);
    cp_commit();

    float o[2][8][4] = {};
    float sum[2][2] = {};

    const int NT = SS / AKT;
    for (int ti = 0; ti < NT; ti++) {
        cp_wait<0>();
        __syncthreads();
        if (ti + 1 < NT) { issue(ti + 1, (ti + 1) & 1); cp_commit(); }

        const uint32_t kb = sKu + (uint32_t)(ti & 1) * 8192;
        const uint32_t vb = sVu + (uint32_t)(ti & 1) * 8192;

        uint32_t sh[2][8][2] = {};
        #pragma unroll
        for (int ks = 0; ks < 4; ks++) {
            uint32_t af[2][4];
            #pragma unroll
            for (int mt = 0; mt < 2; mt++) {
                int row = wrow + mt * 16 + (lane & 15);
                int j = 2 * ks + ((lane >> 4) & 1);
                ldsm4(af[mt], swz(sQu, row, j));
            }
            #pragma unroll
            for (int ntp = 0; ntp < 4; ntp++) {
                uint32_t bf[4];
                int row = ntp * 16 + ((lane >> 4) & 1) * 8 + (lane & 7);
                int j = 2 * ks + ((lane >> 3) & 1);
                ldsm4(bf, swz(kb, row, j));
                #pragma unroll
                for (int mt = 0; mt < 2; mt++) {
                    mma_h16(sh[mt][ntp * 2    ], af[mt], bf[0], bf[1]);
                    mma_h16(sh[mt][ntp * 2 + 1], af[mt], bf[2], bf[3]);
                }
            }
        }

        #pragma unroll
        for (int mt = 0; mt < 2; mt++) {
            __half2 t0 = __float2half2_rn(0.0f), t1 = __float2half2_rn(0.0f);
            #pragma unroll
            for (int nt = 0; nt < 8; nt++) {
                sh[mt][nt][0] = ex2h2(sh[mt][nt][0]);
                sh[mt][nt][1] = ex2h2(sh[mt][nt][1]);
                t0 = __hadd2(t0, *(__half2*)&sh[mt][nt][0]);
                t1 = __hadd2(t1, *(__half2*)&sh[mt][nt][1]);
            }
            float2 f0 = __half22float2(t0), f1 = __half22float2(t1);
            sum[mt][0] += f0.x + f0.y;
            sum[mt][1] += f1.x + f1.y;
        }

        #pragma unroll
        for (int j = 0; j < 4; j++) {
            #pragma unroll
            for (int ntp = 0; ntp < 4; ntp++) {
                uint32_t bf[4];
                int row = j * 16 + ((lane >> 3) & 1) * 8 + (lane & 7);
                int jj = 2 * ntp + ((lane >> 4) & 1);
                ldsm4t(bf, swz(vb, row, jj));
                #pragma unroll
                for (int mt = 0; mt < 2; mt++) {
                    uint32_t af[4] = { sh[mt][2*j][0], sh[mt][2*j][1],
                                       sh[mt][2*j+1][0], sh[mt][2*j+1][1] };
                    mma_f16(o[mt][ntp * 2    ], af, bf[0], bf[1]);
                    mma_f16(o[mt][ntp * 2 + 1], af, bf[2], bf[3]);
                }
            }
        }
    }

    #pragma unroll
    for (int mt = 0; mt < 2; mt++) {
        #pragma unroll
        for (int hh = 0; hh < 2; hh++) {
            sum[mt][hh] += __shfl_xor_sync(0xFFFFFFFFu, sum[mt][hh], 1);
            sum[mt][hh] += __shfl_xor_sync(0xFFFFFFFFu, sum[mt][hh], 2);
        }
    }

    #pragma unroll
    for (int mt = 0; mt < 2; mt++) {
        float inv0 = 1.0f / sum[mt][0], inv1 = 1.0f / sum[mt][1];
        #pragma unroll
        for (int nt = 0; nt < 8; nt++) {
            int d = nt * 8 + 2 * tig;
            size_t r0i = base + (size_t)(q0 + wrow + mt * 16 + g    ) * DD + d;
            size_t r1i = base + (size_t)(q0 + wrow + mt * 16 + g + 8) * DD + d;
            *(__half2*)&O[r0i] = __floats2half2_rn(o[mt][nt][0] * inv0, o[mt][nt][1] * inv0);
            *(__half2*)&O[r1i] = __floats2half2_rn(o[mt][nt][2] * inv1, o[mt][nt][3] * inv1);
        }
    }
}

// ---------------------------------------------------------------------------
extern "C" void kernel_launch(void* const* d_in, const int* in_sizes, int n_in,
                              void* d_out, int out_size) {
    const float* x     = (const float*)d_in[0];
    const float* wq    = (const float*)d_in[1];
    const float* wk    = (const float*)d_in[2];
    const float* wv    = (const float*)d_in[3];
    const float* wo    = (const float*)d_in[4];
    const float* bo    = (const float*)d_in[5];
    const float* gamma = (const float*)d_in[6];
    const float* beta  = (const float*)d_in[7];
    float* out = (float*)d_out;

    __half *pxh, *pwh, *pqh, *pkh, *pvh, *pctxh;
    cudaGetSymbolAddress((void**)&pxh,   g_xh);
    cudaGetSymbolAddress((void**)&pwh,   g_wh);
    cudaGetSymbolAddress((void**)&pqh,   g_qh);
    cudaGetSymbolAddress((void**)&pkh,   g_kh);
    cudaGetSymbolAddress((void**)&pvh,   g_vh);
    cudaGetSymbolAddress((void**)&pctxh, g_ctxh);

    cudaFuncSetAttribute(gemm_qkv,    cudaFuncAttributeMaxDynamicSharedMemorySize, GEMM_SMEM);
    cudaFuncSetAttribute(gemm_out_ln, cudaFuncAttributeMaxDynamicSharedMemorySize, GEMM_SMEM);
    cudaFuncSetAttribute(attn_h,      cudaFuncAttributeMaxDynamicSharedMemorySize, ATTN_SMEM);

    cvt_all<<<(XN4 + 4 * WN4) / 256, 256>>>(x, wq, wk, wv, wo, pxh, pwh);

    dim3 qkvgrid(DD / GBN, BS / GBM, 3);
    gemm_qkv<<<qkvgrid, 256, GEMM_SMEM>>>(pxh, pwh, pqh, pkh, pvh);

    dim3 agrid(SS / AQT, BB * HH);
    attn_h<<<agrid, 128, ATTN_SMEM>>>(pqh, pkh, pvh, pctxh);

    // output projection + bias + residual + fused LayerNorm (push-model LN)
    dim3 ogrid(DD / GBN, BS / GBM);
    gemm_out_ln<<<ogrid, 256, GEMM_SMEM>>>(pctxh, pwh + (size_t)3 * DD * DD,
                                           bo, x, gamma, beta, out);
}